// round 14
// baseline (speedup 1.0000x reference)
#include <cuda_runtime.h>
#include <stdint.h>

// BATCH=128, BUFFER_SIZE=16, IMG4 = 128*128*3/4 = 12288 float4 per image.
// out[m] = combined[m/16 + 1 + m%16], combined = concat(buffer[16], inputs[128]).
//
// Scatter form: source combined[j] (j in 1..143) lands at output images
// m = 16*(j-1) - 15*k for k in [max(0,j-128), min(15,j-1)]  (<=16 dests).
// Loads each source float4 once; output written with evict-first stores.
//
// Persistent single-wave launch: exactly 148 SMs * 8 resident CTAs = 1184
// blocks, grid-striding over 3432 fine work items (143 j x 24 chunks of 512
// float4). Per-block item count is 2 or 3 -> <=3.5% imbalance, no partial
// waves (the R7 version had a 45%-occupied second wave).

#define KBUF 16
#define IMG4 12288
#define CHUNK4 512                 // float4 per item
#define CHUNKS 24                  // items per source image (24*512 = 12288)
#define NITEMS (143 * CHUNKS)      // 3432
#define NBLK 1184                  // 148 SMs * 8 CTAs -> one exact wave

__global__ __launch_bounds__(256, 8) void image_buffer_scatter(
    const float4* __restrict__ inputs,   // [128, IMG4]
    const float4* __restrict__ buffer,   // [16,  IMG4]
    float4* __restrict__ out)            // [2048, IMG4]
{
    const int tid = threadIdx.x;

    for (int item = blockIdx.x; item < NITEMS; item += NBLK) {
        const int jm1 = item / CHUNKS;           // j-1, 0..142 (const-div -> mul/shift)
        const int c   = item - jm1 * CHUNKS;     // chunk, 0..23
        const int j   = jm1 + 1;                 // combined index, 1..143

        const float4* __restrict__ srcimg = (j < KBUF)
            ? (buffer + j * IMG4)
            : (inputs + (j - KBUF) * IMG4);

        const int base = c * CHUNK4 + tid;       // 256 thr * 2 = 512 coverage ✓

        // Load once (2 independent float4; L2-resident after cold miss).
        const float4 v0 = srcimg[base];
        const float4 v1 = srcimg[base + 256];

        const int k_lo = (j - 128 > 0) ? (j - 128) : 0;
        const int k_hi = (j - 1 < 15) ? (j - 1) : 15;

        // Destination image m = 16*(j-1) - 15*k; step -15*IMG4 per k.
        int64_t doff = (int64_t)(16 * jm1 - 15 * k_lo) * IMG4 + base;
        #pragma unroll 4
        for (int k = k_lo; k <= k_hi; ++k) {
            __stcs(out + doff,       v0);
            __stcs(out + doff + 256, v1);
            doff -= (int64_t)15 * IMG4;
        }
    }
}

extern "C" void kernel_launch(void* const* d_in, const int* in_sizes, int n_in,
                              void* d_out, int out_size) {
    const float4* inputs = (const float4*)d_in[0];
    const float4* buffer = (const float4*)d_in[1];
    float4* out = (float4*)d_out;

    image_buffer_scatter<<<NBLK, 256>>>(inputs, buffer, out);
}

// round 15
// speedup vs baseline: 1.0683x; 1.0683x over previous
#include <cuda_runtime.h>
#include <stdint.h>

// BATCH=128, BUFFER_SIZE=16, IMG = 128*128*3 = 49152 floats = 12288 float4
// out[m] = combined[m/16 + 1 + m%16], combined = concat(buffer, inputs)
//
// Gather form (beats scatter on this chip: R7/R14 scatters regressed).
// Grid: y = output image m (0..2047), x = chunk (0..5) of 2048 float4.
// Block: 256 threads; each thread moves 8 float4 at stride 256 (MLP=8).
// Loads: __ldcg — bypass L1 (reuse is cross-SM, lives in L2; load wavefronts
//        were contending with stores in L1tex: L1=68.8% ~= DRAM=71%).
// Stores: __stcs — evict-first; output is never re-read.

#define KBUF 16
#define IMG4 12288
#define CHUNK4 2048   // float4 per block (6 chunks per image)

__global__ __launch_bounds__(256) void image_buffer_gather(
    const float4* __restrict__ inputs,   // [128, IMG4]
    const float4* __restrict__ buffer,   // [16,  IMG4]
    float4* __restrict__ out)            // [2048, IMG4]
{
    const int m = blockIdx.y;            // output image index, 0..2047
    const int i = m >> 4;
    const int k = m & 15;
    const int j = i + 1 + k;             // combined index, 1..143 (block-uniform)

    const float4* __restrict__ srcimg = (j < KBUF)
        ? (buffer + j * IMG4)
        : (inputs + (j - KBUF) * IMG4);

    const int base = blockIdx.x * CHUNK4 + threadIdx.x;
    const float4* __restrict__ src = srcimg + base;
    float4* __restrict__ dst = out + (int64_t)m * IMG4 + base;

    // 8 independent L1-bypassing loads, then 8 streaming stores.
    float4 a0 = __ldcg(src + 0 * 256);
    float4 a1 = __ldcg(src + 1 * 256);
    float4 a2 = __ldcg(src + 2 * 256);
    float4 a3 = __ldcg(src + 3 * 256);
    float4 a4 = __ldcg(src + 4 * 256);
    float4 a5 = __ldcg(src + 5 * 256);
    float4 a6 = __ldcg(src + 6 * 256);
    float4 a7 = __ldcg(src + 7 * 256);
    __stcs(dst + 0 * 256, a0);
    __stcs(dst + 1 * 256, a1);
    __stcs(dst + 2 * 256, a2);
    __stcs(dst + 3 * 256, a3);
    __stcs(dst + 4 * 256, a4);
    __stcs(dst + 5 * 256, a5);
    __stcs(dst + 6 * 256, a6);
    __stcs(dst + 7 * 256, a7);
}

extern "C" void kernel_launch(void* const* d_in, const int* in_sizes, int n_in,
                              void* d_out, int out_size) {
    const float4* inputs = (const float4*)d_in[0];
    const float4* buffer = (const float4*)d_in[1];
    float4* out = (float4*)d_out;

    dim3 grid(6, 2048);   // 6 chunks x 2048 output images = 12288 blocks
    image_buffer_gather<<<grid, 256>>>(inputs, buffer, out);
}